// round 6
// baseline (speedup 1.0000x reference)
#include <cuda_runtime.h>

// ---------------------------------------------------------------------------
// DLinear_436: per-pixel 48->48 linear map with (hc,wc) position-class weights.
// Trend (moving avg, window 25 >= 2T) is affine in t and folded ENTIRELY into
// the weight table:  W'[o,t,c] = Ws_eff + D0/25 + [t==0](12D0-D1)/25
//                                        + [t==11](D0+D1)/25
// Prep: separable two-stage fold (i axis once, then j axis per class).
// Main: 256 blocks x 512 threads, block = 8 rows of one hc class, 1 px/thread
//   (x fits in 48 regs -> NO SPILLS; R5's 2px/thread hit the 128-reg cap and
//   spilled).  Weights in smem (113KB, warp-uniform broadcast LDS), direct
//   LDG/STG (64B-strided lanes; lines shared across the block's interleaved
//   classes so DRAM traffic stays ~1x).  One __syncthreads total.
// ---------------------------------------------------------------------------

#define T_IN 12
#define HW   4096
#define NO   48
#define TC   48
#define NCLS 144

#define CLS_STRIDE 2320                  // floats per class (mod 32 == 16)
#define OFF_SB (12 * CLS_STRIDE)         // 27840
#define SMEM_FLOATS (OFF_SB + 576)       // 28416
#define SMEM_BYTES  (SMEM_FLOATS * 4)    // 113664

// Final per-class tables
__device__ float gWc[NCLS][NO][TC];
__device__ float gBc[NCLS][NO];
// Intermediate separable-fold tables
__device__ float gAs [12][NO][8][TC];    // i-folded w_s      [hc][o][j][tc]
__device__ float gAd [12][NO][8][TC];    // i-folded (w_t-w_s)
__device__ float gD0h[12][NO][8][4];     // sum_t gAd         [hc][o][j][c]
__device__ float gD1h[12][NO][8][4];     // sum_t t*gAd

typedef unsigned long long u64;
#define FMA2(d,a,b,c) asm("fma.rn.f32x2 %0, %1, %2, %3;" : "=l"(d) : "l"(a), "l"(b), "l"(c))
#define ADD2(d,a,b)   asm("add.rn.f32x2 %0, %1, %2;"     : "=l"(d) : "l"(a), "l"(b))
#define UNPACK2(lo,hi,v) asm("mov.b64 {%0, %1}, %2;" : "=f"(lo), "=f"(hi) : "l"(v))

__device__ __forceinline__ int class_ilist(int hc, int idx[2]) {
    if (hc < 4)  { idx[0] = hc;                  return 1; }
    if (hc < 8)  { idx[0] = hc - 4; idx[1] = hc; return 2; }
    idx[0] = hc - 4;                             return 1;
}

// ---------------------------------------------------------------------------
// prepA: fold the i axis for all 12 hc classes at once.  18432 threads.
// ---------------------------------------------------------------------------
__global__ void dlinear_prepA(const float* __restrict__ w_s,
                              const float* __restrict__ w_t) {
    int n = blockIdx.x * blockDim.x + threadIdx.x;
    if (n >= NO * T_IN * 4 * 8) return;
    int j  = n & 7;
    int tc_row = n >> 3;            // (o*12+t)*4+c
    int t  = (n >> 5) % 12;
    int o  = (n >> 5) / 12;
    int c  = (n >> 3) & 3;
    int tc = t * 4 + c;

    int base = tc_row * 64 + j;
    float v[8], d[8];
    #pragma unroll
    for (int i = 0; i < 8; i++) {
        float a = w_s[base + 8 * i];
        float b = w_t[base + 8 * i];
        v[i] = a;
        d[i] = b - a;
    }
    #pragma unroll
    for (int m = 0; m < 4; m++) {
        gAs[m][o][j][tc]     = v[m];
        gAs[m + 4][o][j][tc] = v[m] + v[m + 4];
        gAs[m + 8][o][j][tc] = v[m + 4];
        gAd[m][o][j][tc]     = d[m];
        gAd[m + 4][o][j][tc] = d[m] + d[m + 4];
        gAd[m + 8][o][j][tc] = d[m + 4];
    }
}

// ---------------------------------------------------------------------------
// prepA2: (a) t-reduce gAd -> gD0h/gD1h  (b) bias fold -> gBc
// ---------------------------------------------------------------------------
__global__ void dlinear_prepA2(const float* __restrict__ b_s,
                               const float* __restrict__ b_t) {
    int n = blockIdx.x * blockDim.x + threadIdx.x;
    if (n < 12 * NO * 8 * 4) {
        int c = n & 3, j = (n >> 2) & 7;
        int rest = n >> 5;
        int o = rest % NO, hc = rest / NO;
        float d0 = 0.f, d1 = 0.f;
        #pragma unroll
        for (int t = 0; t < T_IN; t++) {
            float d = gAd[hc][o][j][t * 4 + c];
            d0 += d;
            d1 += (float)t * d;
        }
        gD0h[hc][o][j][c] = d0;
        gD1h[hc][o][j][c] = d1;
        return;
    }
    int m = n - 12 * NO * 8 * 4;
    if (m < NCLS * NO) {
        int o = m % NO, cls = m / NO;
        int hc = cls / 12, wc = cls % 12;
        int il[2], jl[2];
        int ni = class_ilist(hc, il), nj = class_ilist(wc, jl);
        float s = 0.f;
        for (int a = 0; a < ni; a++)
            for (int e = 0; e < nj; e++) {
                int off = o * 64 + il[a] * 8 + jl[e];
                s += b_s[off] + b_t[off];
            }
        gBc[cls][o] = s;
    }
}

// ---------------------------------------------------------------------------
// prepB: fold the j axis per class + absorb trend -> gWc.  331776 threads.
// ---------------------------------------------------------------------------
__global__ void dlinear_prepB() {
    int n = blockIdx.x * blockDim.x + threadIdx.x;
    if (n >= NCLS * NO * TC) return;
    int tc = n % TC;
    int o  = (n / TC) % NO;
    int cls = n / (NO * TC);
    int hc = cls / 12, wc = cls % 12;
    int t = tc >> 2, c = tc & 3;

    int jl[2];
    int nj = class_ilist(wc, jl);

    float s = 0.f, d0 = 0.f, d1 = 0.f;
    for (int e = 0; e < nj; e++) {
        int j = jl[e];
        s  += gAs [hc][o][j][tc];
        d0 += gD0h[hc][o][j][c];
        d1 += gD1h[hc][o][j][c];
    }
    float wv = s + (1.f / 25.f) * d0;
    if (t == 0)  wv += (1.f / 25.f) * (12.f * d0 - d1);
    if (t == 11) wv += (1.f / 25.f) * (d0 + d1);
    gWc[cls][o][tc] = wv;
}

// ---------------------------------------------------------------------------
// Main.  256 blocks x 512 threads.  Block = 8 rows (b,h) of one hc class.
//   bid < 224 : interior hc = 4 + bid/56, rows rho0=(bid%56)*8 of 448
//   bid >= 224: edge e2=bid-224, g=e2>>2, hc = g<4 ? g : g+4, rho0=(e2&3)*8
// Thread -> one wc class + 1 pixel.
//   tid < 448 : interior class c=tid/112, u=tid%112: r=u/14, k=u%14, w=4+4k+c
//   tid >= 448: edge e=(tid-448)/8, v=(tid-448)%8: r=v, w=class column
// ---------------------------------------------------------------------------
__global__ __launch_bounds__(512, 1)
void dlinear_main_kernel(const float* __restrict__ x, float* __restrict__ out) {
    extern __shared__ float sm[];
    const int tid = threadIdx.x;
    const int bid = blockIdx.x;

    int hc, rho0;
    if (bid < 224) { int a = bid / 56; hc = 4 + a; rho0 = (bid - a * 56) * 8; }
    else { int e2 = bid - 224; int g = e2 >> 2; hc = (g < 4) ? g : g + 4; rho0 = (e2 & 3) * 8; }

    // ---- weights + bias -> smem
    {
        const float4* srcW = (const float4*)&gWc[hc * 12][0][0];
        for (int i = tid; i < 12 * 576; i += 512) {
            int c = i / 576, q = i - c * 576;
            *((float4*)(sm + c * CLS_STRIDE) + q) = srcW[i];
        }
        const float* srcB = &gBc[hc * 12][0];
        sm[OFF_SB + tid] = srcB[tid];
        if (tid < 64) sm[OFF_SB + 512 + tid] = srcB[512 + tid];
    }

    // ---- thread -> class + pixel row
    int wc, r, w;
    if (tid < 448) {
        int c = tid / 112;
        int u = tid - c * 112;
        wc = 4 + c;
        r = u / 14;
        int k = u - r * 14;
        w = 4 + 4 * k + c;
    } else {
        int u = tid - 448;
        int e = u >> 3;
        wc = (e < 4) ? e : 4 + e;
        r = u & 7;
        w = (wc < 4) ? wc : 52 + wc;   // wc>=8 -> 60 + (wc-8)
    }

    int gidx;
    {
        int rho = rho0 + r;
        int b, h;
        if (hc < 4)      { b = rho; h = hc; }
        else if (hc < 8) { b = rho / 14; h = (hc - 4) + 4 * (1 + rho - b * 14); }
        else             { b = rho; h = hc + 52; }
        gidx = b * T_IN * HW + h * 64 + w;   // in float4 (16B) units
    }

    __syncthreads();

    // ---- front-batched direct loads of x[t][c] (float4 = (c0..c3) per t)
    u64 x2[24];
    const ulonglong2* xg = (const ulonglong2*)x;
    #pragma unroll
    for (int t = 0; t < T_IN; t++) {
        ulonglong2 v = xg[gidx + t * HW];
        x2[2 * t] = v.x;  x2[2 * t + 1] = v.y;
    }

    // ---- 48 outputs: warp-uniform weight broadcast, direct STG
    const float* wb = sm + wc * CLS_STRIDE;
    const float4* bb4 = (const float4*)(sm + OFF_SB + wc * NO);
    float4* og = (float4*)out;

    #pragma unroll 1
    for (int to = 0; to < 12; to++) {
        float4 bias = bb4[to];
        const float* bp = (const float*)&bias;
        float res[4];
        #pragma unroll
        for (int co = 0; co < 4; co++) {
            const int o = to * 4 + co;
            const ulonglong2* wr = (const ulonglong2*)(wb + o * TC);
            u64 a0 = 0, b0 = 0;
            #pragma unroll
            for (int q = 0; q < 6; q++) {
                ulonglong2 w0 = wr[2 * q];
                ulonglong2 w1 = wr[2 * q + 1];
                FMA2(a0, x2[4 * q],     w0.x, a0);
                FMA2(b0, x2[4 * q + 1], w0.y, b0);
                FMA2(a0, x2[4 * q + 2], w1.x, a0);
                FMA2(b0, x2[4 * q + 3], w1.y, b0);
            }
            float lo, hi;
            ADD2(a0, a0, b0); UNPACK2(lo, hi, a0); res[co] = bp[co] + lo + hi;
        }
        og[gidx + to * HW] = make_float4(res[0], res[1], res[2], res[3]);
    }
}

// ---------------------------------------------------------------------------
extern "C" void kernel_launch(void* const* d_in, const int* in_sizes, int n_in,
                              void* d_out, int out_size) {
    const float* x   = (const float*)d_in[0];
    const float* w_s = (const float*)d_in[1];
    const float* b_s = (const float*)d_in[2];
    const float* w_t = (const float*)d_in[3];
    const float* b_t = (const float*)d_in[4];
    float* out = (float*)d_out;

    cudaFuncSetAttribute(dlinear_main_kernel,
                         cudaFuncAttributeMaxDynamicSharedMemorySize, SMEM_BYTES);

    dlinear_prepA <<<72, 256>>>(w_s, w_t);                  // 18432 threads
    dlinear_prepA2<<<100, 256>>>(b_s, b_t);                 // 18432 + 6912
    dlinear_prepB <<<1296, 256>>>();                        // 331776 threads
    dlinear_main_kernel<<<256, 512, SMEM_BYTES>>>(x, out);
}

// round 7
// speedup vs baseline: 1.2131x; 1.2131x over previous
#include <cuda_runtime.h>

// ---------------------------------------------------------------------------
// DLinear_436: per-pixel 48->48 linear map with (hc,wc) position-class weights.
// Trend (moving avg, window 25 >= 2T) is affine in t and folded ENTIRELY into
// the weight table:  W'[o,t,c] = Ws_eff + D0/25 + [t==0](12D0-D1)/25
//                                        + [t==11](D0+D1)/25
// Prep: separable two-stage fold (i axis once, then j axis per class).
// Main: 256 blocks x 256 threads, launch_bounds(256,1) -> up to 255 regs, so
//   2 px/thread (96 regs of x) does NOT spill (R5's 512-thread version capped
//   at 128 regs and spilled; R6's 1px/thread doubled the per-FMA LDS cost).
//   Block = 8 rows of one hc class.  Weights in smem (113KB, warp-uniform
//   broadcast LDS), direct LDG/STG.  One __syncthreads total.
// ---------------------------------------------------------------------------

#define T_IN 12
#define HW   4096
#define NO   48
#define TC   48
#define NCLS 144

#define CLS_STRIDE 2320                  // floats per class (mod 32 == 16)
#define OFF_SB (12 * CLS_STRIDE)         // 27840
#define SMEM_FLOATS (OFF_SB + 576)       // 28416
#define SMEM_BYTES  (SMEM_FLOATS * 4)    // 113664

// Final per-class tables
__device__ float gWc[NCLS][NO][TC];
__device__ float gBc[NCLS][NO];
// Intermediate separable-fold tables
__device__ float gAs [12][NO][8][TC];    // i-folded w_s      [hc][o][j][tc]
__device__ float gAd [12][NO][8][TC];    // i-folded (w_t-w_s)
__device__ float gD0h[12][NO][8][4];     // sum_t gAd         [hc][o][j][c]
__device__ float gD1h[12][NO][8][4];     // sum_t t*gAd

typedef unsigned long long u64;
#define FMA2(d,a,b,c) asm("fma.rn.f32x2 %0, %1, %2, %3;" : "=l"(d) : "l"(a), "l"(b), "l"(c))
#define ADD2(d,a,b)   asm("add.rn.f32x2 %0, %1, %2;"     : "=l"(d) : "l"(a), "l"(b))
#define UNPACK2(lo,hi,v) asm("mov.b64 {%0, %1}, %2;" : "=f"(lo), "=f"(hi) : "l"(v))

__device__ __forceinline__ int class_ilist(int hc, int idx[2]) {
    if (hc < 4)  { idx[0] = hc;                  return 1; }
    if (hc < 8)  { idx[0] = hc - 4; idx[1] = hc; return 2; }
    idx[0] = hc - 4;                             return 1;
}

// ---------------------------------------------------------------------------
// prepA: fold the i axis for all 12 hc classes at once.  18432 threads.
// ---------------------------------------------------------------------------
__global__ void dlinear_prepA(const float* __restrict__ w_s,
                              const float* __restrict__ w_t) {
    int n = blockIdx.x * blockDim.x + threadIdx.x;
    if (n >= NO * T_IN * 4 * 8) return;
    int j  = n & 7;
    int tc_row = n >> 3;            // (o*12+t)*4+c
    int t  = (n >> 5) % 12;
    int o  = (n >> 5) / 12;
    int c  = (n >> 3) & 3;
    int tc = t * 4 + c;

    int base = tc_row * 64 + j;
    float v[8], d[8];
    #pragma unroll
    for (int i = 0; i < 8; i++) {
        float a = w_s[base + 8 * i];
        float b = w_t[base + 8 * i];
        v[i] = a;
        d[i] = b - a;
    }
    #pragma unroll
    for (int m = 0; m < 4; m++) {
        gAs[m][o][j][tc]     = v[m];
        gAs[m + 4][o][j][tc] = v[m] + v[m + 4];
        gAs[m + 8][o][j][tc] = v[m + 4];
        gAd[m][o][j][tc]     = d[m];
        gAd[m + 4][o][j][tc] = d[m] + d[m + 4];
        gAd[m + 8][o][j][tc] = d[m + 4];
    }
}

// ---------------------------------------------------------------------------
// prepA2: (a) t-reduce gAd -> gD0h/gD1h  (b) bias fold -> gBc
// ---------------------------------------------------------------------------
__global__ void dlinear_prepA2(const float* __restrict__ b_s,
                               const float* __restrict__ b_t) {
    int n = blockIdx.x * blockDim.x + threadIdx.x;
    if (n < 12 * NO * 8 * 4) {
        int c = n & 3, j = (n >> 2) & 7;
        int rest = n >> 5;
        int o = rest % NO, hc = rest / NO;
        float d0 = 0.f, d1 = 0.f;
        #pragma unroll
        for (int t = 0; t < T_IN; t++) {
            float d = gAd[hc][o][j][t * 4 + c];
            d0 += d;
            d1 += (float)t * d;
        }
        gD0h[hc][o][j][c] = d0;
        gD1h[hc][o][j][c] = d1;
        return;
    }
    int m = n - 12 * NO * 8 * 4;
    if (m < NCLS * NO) {
        int o = m % NO, cls = m / NO;
        int hc = cls / 12, wc = cls % 12;
        int il[2], jl[2];
        int ni = class_ilist(hc, il), nj = class_ilist(wc, jl);
        float s = 0.f;
        for (int a = 0; a < ni; a++)
            for (int e = 0; e < nj; e++) {
                int off = o * 64 + il[a] * 8 + jl[e];
                s += b_s[off] + b_t[off];
            }
        gBc[cls][o] = s;
    }
}

// ---------------------------------------------------------------------------
// prepB: fold the j axis per class + absorb trend -> gWc.  331776 threads.
// ---------------------------------------------------------------------------
__global__ void dlinear_prepB() {
    int n = blockIdx.x * blockDim.x + threadIdx.x;
    if (n >= NCLS * NO * TC) return;
    int tc = n % TC;
    int o  = (n / TC) % NO;
    int cls = n / (NO * TC);
    int hc = cls / 12, wc = cls % 12;
    int t = tc >> 2, c = tc & 3;

    int jl[2];
    int nj = class_ilist(wc, jl);

    float s = 0.f, d0 = 0.f, d1 = 0.f;
    for (int e = 0; e < nj; e++) {
        int j = jl[e];
        s  += gAs [hc][o][j][tc];
        d0 += gD0h[hc][o][j][c];
        d1 += gD1h[hc][o][j][c];
    }
    float wv = s + (1.f / 25.f) * d0;
    if (t == 0)  wv += (1.f / 25.f) * (12.f * d0 - d1);
    if (t == 11) wv += (1.f / 25.f) * (d0 + d1);
    gWc[cls][o][tc] = wv;
}

// ---------------------------------------------------------------------------
// Main.  256 blocks x 256 threads, 2 px/thread.  Block = 8 rows of one hc.
//   bid < 224 : interior hc = 4 + bid/56, rows rho0=(bid%56)*8 of 448
//   bid >= 224: edge e2=bid-224, g=e2>>2, hc = g<4 ? g : g+4, rho0=(e2&3)*8
// Thread -> one wc class + 2 pixels (rows r and r+4, SAME w).
//   tid < 224 : interior c=tid/56, u=tid%56: r=u/14, k=u%14, w=4+4k+c
//   tid >= 224: edge e=(tid-224)/4, r=(tid-224)%4, w=class column
// ---------------------------------------------------------------------------
__global__ __launch_bounds__(256, 1)
void dlinear_main_kernel(const float* __restrict__ x, float* __restrict__ out) {
    extern __shared__ float sm[];
    const int tid = threadIdx.x;
    const int bid = blockIdx.x;

    int hc, rho0;
    if (bid < 224) { int a = bid / 56; hc = 4 + a; rho0 = (bid - a * 56) * 8; }
    else { int e2 = bid - 224; int g = e2 >> 2; hc = (g < 4) ? g : g + 4; rho0 = (e2 & 3) * 8; }

    // ---- weights + bias -> smem
    {
        const float4* srcW = (const float4*)&gWc[hc * 12][0][0];
        for (int i = tid; i < 12 * 576; i += 256) {
            int c = i / 576, q = i - c * 576;
            *((float4*)(sm + c * CLS_STRIDE) + q) = srcW[i];
        }
        const float* srcB = &gBc[hc * 12][0];
        sm[OFF_SB + tid] = srcB[tid];
        sm[OFF_SB + 256 + tid] = srcB[256 + tid];
        if (tid < 64) sm[OFF_SB + 512 + tid] = srcB[512 + tid];
    }

    // ---- thread -> class + 2 pixel rows (r and r+4, same w)
    int wc, r0, w;
    if (tid < 224) {
        int c = tid / 56;
        int u = tid - c * 56;
        wc = 4 + c;
        r0 = u / 14;
        int k = u - r0 * 14;
        w = 4 + 4 * k + c;
    } else {
        int u = tid - 224;
        int e = u >> 2;
        wc = (e < 4) ? e : 4 + e;
        r0 = u & 3;
        w = (wc < 4) ? wc : 52 + wc;   // wc>=8 -> 60 + (wc-8)
    }

    int gidx[2];
    #pragma unroll
    for (int it = 0; it < 2; it++) {
        int rho = rho0 + r0 + it * 4;
        int b, h;
        if (hc < 4)      { b = rho; h = hc; }
        else if (hc < 8) { b = rho / 14; h = (hc - 4) + 4 * (1 + rho - b * 14); }
        else             { b = rho; h = hc + 52; }
        gidx[it] = b * T_IN * HW + h * 64 + w;   // in float4 (16B) units
    }

    __syncthreads();

    // ---- front-batched direct loads of x[t][c] for both pixels
    u64 x2[2][24];
    const ulonglong2* xg = (const ulonglong2*)x;
    #pragma unroll
    for (int t = 0; t < T_IN; t++) {
        ulonglong2 v0 = xg[gidx[0] + t * HW];
        ulonglong2 v1 = xg[gidx[1] + t * HW];
        x2[0][2 * t] = v0.x;  x2[0][2 * t + 1] = v0.y;
        x2[1][2 * t] = v1.x;  x2[1][2 * t + 1] = v1.y;
    }

    // ---- 48 outputs: warp-uniform weight broadcast, direct STG
    const float* wb = sm + wc * CLS_STRIDE;
    const float4* bb4 = (const float4*)(sm + OFF_SB + wc * NO);
    float4* og = (float4*)out;

    #pragma unroll 1
    for (int to = 0; to < 12; to++) {
        float4 bias = bb4[to];
        const float* bp = (const float*)&bias;
        float res0[4], res1[4];
        #pragma unroll
        for (int co = 0; co < 4; co++) {
            const int o = to * 4 + co;
            const ulonglong2* wr = (const ulonglong2*)(wb + o * TC);
            u64 a0 = 0, b0 = 0, a1 = 0, b1 = 0;
            #pragma unroll
            for (int q = 0; q < 6; q++) {
                ulonglong2 w0 = wr[2 * q];
                ulonglong2 w1 = wr[2 * q + 1];
                FMA2(a0, x2[0][4 * q],     w0.x, a0);
                FMA2(b0, x2[0][4 * q + 1], w0.y, b0);
                FMA2(a0, x2[0][4 * q + 2], w1.x, a0);
                FMA2(b0, x2[0][4 * q + 3], w1.y, b0);
                FMA2(a1, x2[1][4 * q],     w0.x, a1);
                FMA2(b1, x2[1][4 * q + 1], w0.y, b1);
                FMA2(a1, x2[1][4 * q + 2], w1.x, a1);
                FMA2(b1, x2[1][4 * q + 3], w1.y, b1);
            }
            float lo, hi;
            ADD2(a0, a0, b0); UNPACK2(lo, hi, a0); res0[co] = bp[co] + lo + hi;
            ADD2(a1, a1, b1); UNPACK2(lo, hi, a1); res1[co] = bp[co] + lo + hi;
        }
        og[gidx[0] + to * HW] = make_float4(res0[0], res0[1], res0[2], res0[3]);
        og[gidx[1] + to * HW] = make_float4(res1[0], res1[1], res1[2], res1[3]);
    }
}

// ---------------------------------------------------------------------------
extern "C" void kernel_launch(void* const* d_in, const int* in_sizes, int n_in,
                              void* d_out, int out_size) {
    const float* x   = (const float*)d_in[0];
    const float* w_s = (const float*)d_in[1];
    const float* b_s = (const float*)d_in[2];
    const float* w_t = (const float*)d_in[3];
    const float* b_t = (const float*)d_in[4];
    float* out = (float*)d_out;

    cudaFuncSetAttribute(dlinear_main_kernel,
                         cudaFuncAttributeMaxDynamicSharedMemorySize, SMEM_BYTES);

    dlinear_prepA <<<72, 256>>>(w_s, w_t);                  // 18432 threads
    dlinear_prepA2<<<100, 256>>>(b_s, b_t);                 // 18432 + 6912
    dlinear_prepB <<<1296, 256>>>();                        // 331776 threads
    dlinear_main_kernel<<<256, 256, SMEM_BYTES>>>(x, out);
}

// round 8
// speedup vs baseline: 1.2183x; 1.0043x over previous
#include <cuda_runtime.h>

// ---------------------------------------------------------------------------
// DLinear_436: per-pixel 48->48 linear map with (hc,wc) position-class weights.
// Trend (moving avg, window 25 >= 2T) is affine in t and folded ENTIRELY into
// the weight table.  Prep: separable fold (i axis once, then j per class),
// writing SLOT-INTERLEAVED tables:
//   gWi4[hc][o][q][slot4][4]  (interior-w classes, slot = w%4,   64B records)
//   gWi8[hc][o][q][slot8][4]  (edge-w classes,     slot = col,  128B records)
// Main: 292 blocks x 256 threads, 2 px/thread.  Lanes are w-CONTIGUOUS
// (coalesced LDG/STG, ~4 wavefronts) and each lane reads its class's weight
// quad from within one 64/128B record -> 1 LDS wavefront.  Best of both.
// ---------------------------------------------------------------------------

#define T_IN 12
#define HW   4096
#define NO   48
#define TC   48
#define NCLS 144

#define SMEM_BYTES ((18432 + 384) * 4)   // edge table + bias = 75264 B

// Slot-interleaved final tables
__device__ float gWi4[12][48][12][4][4];   // [hc][o][q][slot][j]
__device__ float gWi8[12][48][12][8][4];
__device__ float gBi4[12][12][4][4];       // [hc][to][slot][co]
__device__ float gBi8[12][12][8][4];
// Intermediate separable-fold tables
__device__ float gAs [12][NO][8][TC];      // i-folded w_s      [hc][o][j][tc]
__device__ float gAd [12][NO][8][TC];      // i-folded (w_t-w_s)
__device__ float gD0h[12][NO][8][4];       // sum_t gAd         [hc][o][j][c]
__device__ float gD1h[12][NO][8][4];       // sum_t t*gAd

typedef unsigned long long u64;
#define FMA2(d,a,b,c) asm("fma.rn.f32x2 %0, %1, %2, %3;" : "=l"(d) : "l"(a), "l"(b), "l"(c))
#define ADD2(d,a,b)   asm("add.rn.f32x2 %0, %1, %2;"     : "=l"(d) : "l"(a), "l"(b))
#define UNPACK2(lo,hi,v) asm("mov.b64 {%0, %1}, %2;" : "=f"(lo), "=f"(hi) : "l"(v))

__device__ __forceinline__ int class_ilist(int hc, int idx[2]) {
    if (hc < 4)  { idx[0] = hc;                  return 1; }
    if (hc < 8)  { idx[0] = hc - 4; idx[1] = hc; return 2; }
    idx[0] = hc - 4;                             return 1;
}

// ---------------------------------------------------------------------------
// prepA: fold the i axis for all 12 hc classes at once.  18432 threads.
// ---------------------------------------------------------------------------
__global__ void dlinear_prepA(const float* __restrict__ w_s,
                              const float* __restrict__ w_t) {
    int n = blockIdx.x * blockDim.x + threadIdx.x;
    if (n >= NO * T_IN * 4 * 8) return;
    int j  = n & 7;
    int tc_row = n >> 3;            // (o*12+t)*4+c
    int t  = (n >> 5) % 12;
    int o  = (n >> 5) / 12;
    int c  = (n >> 3) & 3;
    int tc = t * 4 + c;

    int base = tc_row * 64 + j;
    float v[8], d[8];
    #pragma unroll
    for (int i = 0; i < 8; i++) {
        float a = w_s[base + 8 * i];
        float b = w_t[base + 8 * i];
        v[i] = a;
        d[i] = b - a;
    }
    #pragma unroll
    for (int m = 0; m < 4; m++) {
        gAs[m][o][j][tc]     = v[m];
        gAs[m + 4][o][j][tc] = v[m] + v[m + 4];
        gAs[m + 8][o][j][tc] = v[m + 4];
        gAd[m][o][j][tc]     = d[m];
        gAd[m + 4][o][j][tc] = d[m] + d[m + 4];
        gAd[m + 8][o][j][tc] = d[m + 4];
    }
}

// ---------------------------------------------------------------------------
// prepA2: (a) t-reduce gAd -> gD0h/gD1h  (b) bias fold -> gBi4/gBi8
// ---------------------------------------------------------------------------
__global__ void dlinear_prepA2(const float* __restrict__ b_s,
                               const float* __restrict__ b_t) {
    int n = blockIdx.x * blockDim.x + threadIdx.x;
    if (n < 12 * NO * 8 * 4) {
        int c = n & 3, j = (n >> 2) & 7;
        int rest = n >> 5;
        int o = rest % NO, hc = rest / NO;
        float d0 = 0.f, d1 = 0.f;
        #pragma unroll
        for (int t = 0; t < T_IN; t++) {
            float d = gAd[hc][o][j][t * 4 + c];
            d0 += d;
            d1 += (float)t * d;
        }
        gD0h[hc][o][j][c] = d0;
        gD1h[hc][o][j][c] = d1;
        return;
    }
    int m = n - 12 * NO * 8 * 4;
    if (m < NCLS * NO) {
        int o = m % NO, cls = m / NO;
        int hc = cls / 12, wc = cls % 12;
        int il[2], jl[2];
        int ni = class_ilist(hc, il), nj = class_ilist(wc, jl);
        float s = 0.f;
        for (int a = 0; a < ni; a++)
            for (int e = 0; e < nj; e++) {
                int off = o * 64 + il[a] * 8 + jl[e];
                s += b_s[off] + b_t[off];
            }
        int to = o >> 2, co = o & 3;
        if (wc >= 4 && wc < 8) gBi4[hc][to][wc - 4][co] = s;
        else if (wc < 4)       gBi8[hc][to][wc][co]     = s;
        else                   gBi8[hc][to][wc - 4][co] = s;
    }
}

// ---------------------------------------------------------------------------
// prepB: fold the j axis per class + absorb trend -> slot-interleaved tables.
// 331776 threads.
// ---------------------------------------------------------------------------
__global__ void dlinear_prepB() {
    int n = blockIdx.x * blockDim.x + threadIdx.x;
    if (n >= NCLS * NO * TC) return;
    int tc = n % TC;
    int o  = (n / TC) % NO;
    int cls = n / (NO * TC);
    int hc = cls / 12, wc = cls % 12;
    int t = tc >> 2, c = tc & 3;

    int jl[2];
    int nj = class_ilist(wc, jl);

    float s = 0.f, d0 = 0.f, d1 = 0.f;
    for (int e = 0; e < nj; e++) {
        int j = jl[e];
        s  += gAs [hc][o][j][tc];
        d0 += gD0h[hc][o][j][c];
        d1 += gD1h[hc][o][j][c];
    }
    float wv = s + (1.f / 25.f) * d0;
    if (t == 0)  wv += (1.f / 25.f) * (12.f * d0 - d1);
    if (t == 11) wv += (1.f / 25.f) * (d0 + d1);

    // weight quad index q == t (tc = t*4 + c), element j == c
    if (wc >= 4 && wc < 8) gWi4[hc][o][t][wc - 4][c] = wv;
    else if (wc < 4)       gWi8[hc][o][t][wc][c]     = wv;
    else                   gWi8[hc][o][t][wc - 4][c] = wv;
}

// ---------------------------------------------------------------------------
// Compute + store, templated on slot count (4 = interior-w, 8 = edge-w).
// ---------------------------------------------------------------------------
template<int NS>
__device__ __forceinline__ void compute_store(
    const float* sm, int slot, const u64 (&x2)[2][24],
    int g0, int g1, float* __restrict__ out)
{
    const ulonglong2* wt = (const ulonglong2*)sm;
    const float4* bt = (const float4*)(sm + 48 * 12 * 4 * NS);
    float4* og = (float4*)out;

    #pragma unroll 1
    for (int to = 0; to < 12; to++) {
        float4 bias = bt[to * NS + slot];
        const float* bp = (const float*)&bias;
        float res0[4], res1[4];
        #pragma unroll
        for (int co = 0; co < 4; co++) {
            const int o = to * 4 + co;
            const ulonglong2* wr = wt + (o * 12) * NS + slot;
            u64 a0 = 0, b0 = 0, a1 = 0, b1 = 0;
            #pragma unroll
            for (int q = 0; q < 12; q++) {
                ulonglong2 wv = wr[q * NS];
                FMA2(a0, x2[0][2 * q],     wv.x, a0);
                FMA2(b0, x2[0][2 * q + 1], wv.y, b0);
                FMA2(a1, x2[1][2 * q],     wv.x, a1);
                FMA2(b1, x2[1][2 * q + 1], wv.y, b1);
            }
            float lo, hi;
            ADD2(a0, a0, b0); UNPACK2(lo, hi, a0); res0[co] = bp[co] + lo + hi;
            ADD2(a1, a1, b1); UNPACK2(lo, hi, a1); res1[co] = bp[co] + lo + hi;
        }
        og[g0 + to * HW] = make_float4(res0[0], res0[1], res0[2], res0[3]);
        og[g1 + to * HW] = make_float4(res1[0], res1[1], res1[2], res1[3]);
    }
}

// ---------------------------------------------------------------------------
// Main.  292 blocks x 256 threads, 2 px/thread, lanes w-contiguous.
//   bid < 256 : interior-w (w in [4,60), 4 classes).  Block = 8 rows of one
//               hc, 448 px, 224 active threads (pairs rows r, r+4).
//     bid<224: hc=4+bid/56, rho0=(bid%56)*8;  else edge-hc, 8 groups of 4.
//   bid >= 256: edge-w (w in {0..3,60..63}, 8 classes).
//     eb<28: interior hc=4+eb/7, 64 rows; else edge hc, 32 rows (128 thr).
// ---------------------------------------------------------------------------
__global__ __launch_bounds__(256, 1)
void dlinear_main_kernel(const float* __restrict__ x, float* __restrict__ out) {
    extern __shared__ float sm[];
    const int tid = threadIdx.x;
    const int bid = blockIdx.x;

    int hc, rho0, half, tabFloats, nbq, active, slot, r, w;
    const float *gtab, *gbias;

    if (bid < 256) {
        tabFloats = 9216; nbq = 48;
        if (bid < 224) { int a = bid / 56; hc = 4 + a; rho0 = (bid - a * 56) * 8; }
        else { int e = bid - 224; int g = e >> 2; hc = (g < 4) ? g : g + 4; rho0 = (e & 3) * 8; }
        half = 4;
        active = (tid < 224);
        int m = active ? tid : 0;
        r = m / 56;
        w = 4 + (m - r * 56);
        slot = w & 3;
        gtab = &gWi4[hc][0][0][0][0]; gbias = &gBi4[hc][0][0][0];
    } else {
        tabFloats = 18432; nbq = 96;
        int eb = bid - 256, R;
        if (eb < 28) { int a = eb / 7; hc = 4 + a; rho0 = (eb - a * 7) * 64; R = 64; }
        else { int e = eb - 28; hc = (e < 4) ? e : e + 4; rho0 = 0; R = 32; }
        half = R >> 1;
        active = (tid < half * 8);
        int m = active ? tid : 0;
        slot = m & 7;
        r = m >> 3;
        w = (slot < 4) ? slot : 56 + slot;
        gtab = &gWi8[hc][0][0][0][0]; gbias = &gBi8[hc][0][0][0];
    }

    // stage weight table + bias into smem (coalesced float4 copies)
    {
        const float4* s4 = (const float4*)gtab;
        float4* d4 = (float4*)sm;
        int nq = tabFloats >> 2;
        for (int i = tid; i < nq; i += 256) d4[i] = s4[i];
        const float4* b4 = (const float4*)gbias;
        float4* db = (float4*)(sm + tabFloats);
        for (int i = tid; i < nbq; i += 256) db[i] = b4[i];
    }

    // pixel addresses for the two rows (r and r+half)
    int g0, g1;
    {
        int gg[2];
        #pragma unroll
        for (int it = 0; it < 2; it++) {
            int rho = rho0 + r + it * half;
            int b, h;
            if (hc < 4)      { b = rho; h = hc; }
            else if (hc < 8) { b = rho / 14; h = (hc - 4) + 4 * (1 + rho - b * 14); }
            else             { b = rho; h = hc + 52; }
            gg[it] = b * T_IN * HW + h * 64 + w;   // in float4 (16B) units
        }
        g0 = gg[0]; g1 = gg[1];
    }

    __syncthreads();
    if (!active) return;

    // front-batched coalesced loads of x[t][c] for both pixels
    u64 x2[2][24];
    const ulonglong2* xg = (const ulonglong2*)x;
    #pragma unroll
    for (int t = 0; t < T_IN; t++) {
        ulonglong2 v0 = xg[g0 + t * HW];
        ulonglong2 v1 = xg[g1 + t * HW];
        x2[0][2 * t] = v0.x;  x2[0][2 * t + 1] = v0.y;
        x2[1][2 * t] = v1.x;  x2[1][2 * t + 1] = v1.y;
    }

    if (bid < 256) compute_store<4>(sm, slot, x2, g0, g1, out);
    else           compute_store<8>(sm, slot, x2, g0, g1, out);
}

// ---------------------------------------------------------------------------
extern "C" void kernel_launch(void* const* d_in, const int* in_sizes, int n_in,
                              void* d_out, int out_size) {
    const float* x   = (const float*)d_in[0];
    const float* w_s = (const float*)d_in[1];
    const float* b_s = (const float*)d_in[2];
    const float* w_t = (const float*)d_in[3];
    const float* b_t = (const float*)d_in[4];
    float* out = (float*)d_out;

    cudaFuncSetAttribute(dlinear_main_kernel,
                         cudaFuncAttributeMaxDynamicSharedMemorySize, SMEM_BYTES);

    dlinear_prepA <<<72, 256>>>(w_s, w_t);                  // 18432 threads
    dlinear_prepA2<<<100, 256>>>(b_s, b_t);                 // 18432 + 6912
    dlinear_prepB <<<1296, 256>>>();                        // 331776 threads
    dlinear_main_kernel<<<292, 256, SMEM_BYTES>>>(x, out);
}

// round 9
// speedup vs baseline: 1.2889x; 1.0580x over previous
#include <cuda_runtime.h>

// ---------------------------------------------------------------------------
// DLinear_436: per-pixel 48->48 linear map with (hc,wc) position-class weights.
// Trend folded entirely into the weight table (affine-in-t moving average).
// Prep (unchanged from R8): separable fold -> slot-interleaved tables:
//   gWi4[hc][o][q][slot4][4]  (interior-w classes, 64B records)
//   gWi8[hc][o][q][slot8][4]  (edge-w classes,    128B records)
// Main (new): 320 blocks x 128 threads, 4 px/thread.  Weight-LDS stream per
// warp (576 LDS.128, the L1 bottleneck) now amortizes over 128 pixels ->
// FMA pipe becomes binding.  launch_bounds(128,2) -> 2 blocks/SM, 8 warps.
// ---------------------------------------------------------------------------

#define T_IN 12
#define HW   4096
#define NO   48
#define TC   48
#define NCLS 144

#define SMEM_BYTES ((18432 + 384) * 4)   // edge table + bias = 75264 B

// Slot-interleaved final tables
__device__ float gWi4[12][48][12][4][4];   // [hc][o][q][slot][j]
__device__ float gWi8[12][48][12][8][4];
__device__ float gBi4[12][12][4][4];       // [hc][to][slot][co]
__device__ float gBi8[12][12][8][4];
// Intermediate separable-fold tables
__device__ float gAs [12][NO][8][TC];      // i-folded w_s      [hc][o][j][tc]
__device__ float gAd [12][NO][8][TC];      // i-folded (w_t-w_s)
__device__ float gD0h[12][NO][8][4];       // sum_t gAd         [hc][o][j][c]
__device__ float gD1h[12][NO][8][4];       // sum_t t*gAd

typedef unsigned long long u64;
#define FMA2(d,a,b,c) asm("fma.rn.f32x2 %0, %1, %2, %3;" : "=l"(d) : "l"(a), "l"(b), "l"(c))
#define ADD2(d,a,b)   asm("add.rn.f32x2 %0, %1, %2;"     : "=l"(d) : "l"(a), "l"(b))
#define UNPACK2(lo,hi,v) asm("mov.b64 {%0, %1}, %2;" : "=f"(lo), "=f"(hi) : "l"(v))

__device__ __forceinline__ int class_ilist(int hc, int idx[2]) {
    if (hc < 4)  { idx[0] = hc;                  return 1; }
    if (hc < 8)  { idx[0] = hc - 4; idx[1] = hc; return 2; }
    idx[0] = hc - 4;                             return 1;
}

// ---------------------------------------------------------------------------
// prepA: fold the i axis for all 12 hc classes at once.  18432 threads.
// ---------------------------------------------------------------------------
__global__ void dlinear_prepA(const float* __restrict__ w_s,
                              const float* __restrict__ w_t) {
    int n = blockIdx.x * blockDim.x + threadIdx.x;
    if (n >= NO * T_IN * 4 * 8) return;
    int j  = n & 7;
    int tc_row = n >> 3;            // (o*12+t)*4+c
    int t  = (n >> 5) % 12;
    int o  = (n >> 5) / 12;
    int c  = (n >> 3) & 3;
    int tc = t * 4 + c;

    int base = tc_row * 64 + j;
    float v[8], d[8];
    #pragma unroll
    for (int i = 0; i < 8; i++) {
        float a = w_s[base + 8 * i];
        float b = w_t[base + 8 * i];
        v[i] = a;
        d[i] = b - a;
    }
    #pragma unroll
    for (int m = 0; m < 4; m++) {
        gAs[m][o][j][tc]     = v[m];
        gAs[m + 4][o][j][tc] = v[m] + v[m + 4];
        gAs[m + 8][o][j][tc] = v[m + 4];
        gAd[m][o][j][tc]     = d[m];
        gAd[m + 4][o][j][tc] = d[m] + d[m + 4];
        gAd[m + 8][o][j][tc] = d[m + 4];
    }
}

// ---------------------------------------------------------------------------
// prepA2: (a) t-reduce gAd -> gD0h/gD1h  (b) bias fold -> gBi4/gBi8
// ---------------------------------------------------------------------------
__global__ void dlinear_prepA2(const float* __restrict__ b_s,
                               const float* __restrict__ b_t) {
    int n = blockIdx.x * blockDim.x + threadIdx.x;
    if (n < 12 * NO * 8 * 4) {
        int c = n & 3, j = (n >> 2) & 7;
        int rest = n >> 5;
        int o = rest % NO, hc = rest / NO;
        float d0 = 0.f, d1 = 0.f;
        #pragma unroll
        for (int t = 0; t < T_IN; t++) {
            float d = gAd[hc][o][j][t * 4 + c];
            d0 += d;
            d1 += (float)t * d;
        }
        gD0h[hc][o][j][c] = d0;
        gD1h[hc][o][j][c] = d1;
        return;
    }
    int m = n - 12 * NO * 8 * 4;
    if (m < NCLS * NO) {
        int o = m % NO, cls = m / NO;
        int hc = cls / 12, wc = cls % 12;
        int il[2], jl[2];
        int ni = class_ilist(hc, il), nj = class_ilist(wc, jl);
        float s = 0.f;
        for (int a = 0; a < ni; a++)
            for (int e = 0; e < nj; e++) {
                int off = o * 64 + il[a] * 8 + jl[e];
                s += b_s[off] + b_t[off];
            }
        int to = o >> 2, co = o & 3;
        if (wc >= 4 && wc < 8) gBi4[hc][to][wc - 4][co] = s;
        else if (wc < 4)       gBi8[hc][to][wc][co]     = s;
        else                   gBi8[hc][to][wc - 4][co] = s;
    }
}

// ---------------------------------------------------------------------------
// prepB: fold the j axis per class + absorb trend -> slot-interleaved tables.
// ---------------------------------------------------------------------------
__global__ void dlinear_prepB() {
    int n = blockIdx.x * blockDim.x + threadIdx.x;
    if (n >= NCLS * NO * TC) return;
    int tc = n % TC;
    int o  = (n / TC) % NO;
    int cls = n / (NO * TC);
    int hc = cls / 12, wc = cls % 12;
    int t = tc >> 2, c = tc & 3;

    int jl[2];
    int nj = class_ilist(wc, jl);

    float s = 0.f, d0 = 0.f, d1 = 0.f;
    for (int e = 0; e < nj; e++) {
        int j = jl[e];
        s  += gAs [hc][o][j][tc];
        d0 += gD0h[hc][o][j][c];
        d1 += gD1h[hc][o][j][c];
    }
    float wv = s + (1.f / 25.f) * d0;
    if (t == 0)  wv += (1.f / 25.f) * (12.f * d0 - d1);
    if (t == 11) wv += (1.f / 25.f) * (d0 + d1);

    if (wc >= 4 && wc < 8) gWi4[hc][o][t][wc - 4][c] = wv;
    else if (wc < 4)       gWi8[hc][o][t][wc][c]     = wv;
    else                   gWi8[hc][o][t][wc - 4][c] = wv;
}

// ---------------------------------------------------------------------------
// Compute + store for 4 pixels, templated on slot count (4 interior, 8 edge).
// ---------------------------------------------------------------------------
template<int NS>
__device__ __forceinline__ void compute_store(
    const float* sm, int slot, const u64 (&x2)[4][24],
    const int (&g)[4], float* __restrict__ out)
{
    const ulonglong2* wt = (const ulonglong2*)sm;
    const float4* bt = (const float4*)(sm + 48 * 12 * 4 * NS);
    float4* og = (float4*)out;

    #pragma unroll 1
    for (int to = 0; to < 12; to++) {
        float4 bias = bt[to * NS + slot];
        const float* bp = (const float*)&bias;
        float res[4][4];
        #pragma unroll
        for (int co = 0; co < 4; co++) {
            const int o = to * 4 + co;
            const ulonglong2* wr = wt + (o * 12) * NS + slot;
            u64 a0 = 0, a1 = 0, a2 = 0, a3 = 0;
            #pragma unroll
            for (int q = 0; q < 12; q++) {
                ulonglong2 wv = wr[q * NS];
                FMA2(a0, x2[0][2 * q],     wv.x, a0);
                FMA2(a1, x2[1][2 * q],     wv.x, a1);
                FMA2(a2, x2[2][2 * q],     wv.x, a2);
                FMA2(a3, x2[3][2 * q],     wv.x, a3);
                FMA2(a0, x2[0][2 * q + 1], wv.y, a0);
                FMA2(a1, x2[1][2 * q + 1], wv.y, a1);
                FMA2(a2, x2[2][2 * q + 1], wv.y, a2);
                FMA2(a3, x2[3][2 * q + 1], wv.y, a3);
            }
            float lo, hi;
            UNPACK2(lo, hi, a0); res[0][co] = bp[co] + lo + hi;
            UNPACK2(lo, hi, a1); res[1][co] = bp[co] + lo + hi;
            UNPACK2(lo, hi, a2); res[2][co] = bp[co] + lo + hi;
            UNPACK2(lo, hi, a3); res[3][co] = bp[co] + lo + hi;
        }
        #pragma unroll
        for (int p = 0; p < 4; p++)
            og[g[p] + to * HW] = make_float4(res[p][0], res[p][1], res[p][2], res[p][3]);
    }
}

// ---------------------------------------------------------------------------
// Main.  320 blocks x 128 threads, 4 px/thread, lanes w-contiguous.
//   bid < 256 : interior-w (w in [4,60)).  Block = 8 rows of one hc, 448 px,
//               112 active threads; pixel rows r + {0,2,4,6}.
//     bid<224: hc=4+bid/56, rho0=(bid%56)*8
//     else   : e=bid-224, g=e>>2, hc=(g<4)?g:g+4, rho0=(e&3)*8
//   bid >= 256: edge-w (w in {0..3,60..63}).  Block = 32 rows, 256 px,
//               64 active threads; pixel rows r + {0,8,16,24}.
//     eb<56: hc=4+eb/14, rho0=(eb%14)*32;  else edge hc, rho0=0.
// ---------------------------------------------------------------------------
__global__ __launch_bounds__(128, 2)
void dlinear_main_kernel(const float* __restrict__ x, float* __restrict__ out) {
    extern __shared__ float sm[];
    const int tid = threadIdx.x;
    const int bid = blockIdx.x;

    int hc, rho0, stride, tabFloats, nbq, active, slot, r, w;
    const float *gtab, *gbias;

    if (bid < 256) {
        tabFloats = 9216; nbq = 48; stride = 2;
        if (bid < 224) { int a = bid / 56; hc = 4 + a; rho0 = (bid - a * 56) * 8; }
        else { int e = bid - 224; int g = e >> 2; hc = (g < 4) ? g : g + 4; rho0 = (e & 3) * 8; }
        active = (tid < 112);
        int m = active ? tid : 0;
        r = m / 56;
        w = 4 + (m - r * 56);
        slot = w & 3;
        gtab = &gWi4[hc][0][0][0][0]; gbias = &gBi4[hc][0][0][0];
    } else {
        tabFloats = 18432; nbq = 96; stride = 8;
        int eb = bid - 256;
        if (eb < 56) { int a = eb / 14; hc = 4 + a; rho0 = (eb - a * 14) * 32; }
        else { int e = eb - 56; hc = (e < 4) ? e : e + 4; rho0 = 0; }
        active = (tid < 64);
        int m = active ? tid : 0;
        slot = m & 7;
        r = m >> 3;
        w = (slot < 4) ? slot : 56 + slot;
        gtab = &gWi8[hc][0][0][0][0]; gbias = &gBi8[hc][0][0][0];
    }

    // stage weight table + bias into smem (coalesced float4 copies)
    {
        const float4* s4 = (const float4*)gtab;
        float4* d4 = (float4*)sm;
        int nq = tabFloats >> 2;
        for (int i = tid; i < nq; i += 128) d4[i] = s4[i];
        const float4* b4 = (const float4*)gbias;
        float4* db = (float4*)(sm + tabFloats);
        for (int i = tid; i < nbq; i += 128) db[i] = b4[i];
    }

    // pixel addresses (rows r + it*stride)
    int g[4];
    #pragma unroll
    for (int it = 0; it < 4; it++) {
        int rho = rho0 + r + it * stride;
        int b, h;
        if (hc < 4)      { b = rho; h = hc; }
        else if (hc < 8) { b = rho / 14; h = (hc - 4) + 4 * (1 + rho - b * 14); }
        else             { b = rho; h = hc + 52; }
        g[it] = b * T_IN * HW + h * 64 + w;   // in float4 (16B) units
    }

    __syncthreads();
    if (!active) return;

    // front-batched coalesced loads of x[t][c] for all 4 pixels
    u64 x2[4][24];
    const ulonglong2* xg = (const ulonglong2*)x;
    #pragma unroll
    for (int t = 0; t < T_IN; t++) {
        #pragma unroll
        for (int p = 0; p < 4; p++) {
            ulonglong2 v = xg[g[p] + t * HW];
            x2[p][2 * t] = v.x;  x2[p][2 * t + 1] = v.y;
        }
    }

    if (bid < 256) compute_store<4>(sm, slot, x2, g, out);
    else           compute_store<8>(sm, slot, x2, g, out);
}

// ---------------------------------------------------------------------------
extern "C" void kernel_launch(void* const* d_in, const int* in_sizes, int n_in,
                              void* d_out, int out_size) {
    const float* x   = (const float*)d_in[0];
    const float* w_s = (const float*)d_in[1];
    const float* b_s = (const float*)d_in[2];
    const float* w_t = (const float*)d_in[3];
    const float* b_t = (const float*)d_in[4];
    float* out = (float*)d_out;

    cudaFuncSetAttribute(dlinear_main_kernel,
                         cudaFuncAttributeMaxDynamicSharedMemorySize, SMEM_BYTES);

    dlinear_prepA <<<72, 256>>>(w_s, w_t);                  // 18432 threads
    dlinear_prepA2<<<100, 256>>>(b_s, b_t);                 // 18432 + 6912
    dlinear_prepB <<<1296, 256>>>();                        // 331776 threads
    dlinear_main_kernel<<<320, 128, SMEM_BYTES>>>(x, out);
}

// round 10
// speedup vs baseline: 1.6800x; 1.3034x over previous
#include <cuda_runtime.h>

// ---------------------------------------------------------------------------
// DLinear_436: per-pixel 48->48 linear map with (hc,wc) position-class weights.
// Trend (window-25 moving avg over T=12, affine in t) folded entirely into the
// weight table by prep.  Prep: separable fold -> 12-slot interleaved table
//   gWi12[hc][o][q][wc][4]   (192B record covers ALL 12 wc classes)
// Main: 128 blocks x 256 threads, 4 px/thread, ONE wave, ALL threads active.
//   Block = (h fixed, 16 b's) -> hc uniform, lanes w-contiguous (coalesced
//   LDG/STG).  Each lane reads its wc's weight quad from within the 192B
//   record (~2 smem phases).  FMA2 pipe is the binding resource.
// ---------------------------------------------------------------------------

#define T_IN 12
#define HW   4096
#define NO   48
#define TC   48
#define NCLS 144

#define TAB_FLOATS (48 * 12 * 12 * 4)          // 27648
#define SMEM_FLOATS (TAB_FLOATS + 576)         // + bias = 28224
#define SMEM_BYTES  (SMEM_FLOATS * 4)          // 112896

// Final tables
__device__ float gWi12[12][48][12][12][4];     // [hc][o][q][wc][c]
__device__ float gBi12[12][12][12][4];         // [hc][to][wc][co]
// Intermediate separable-fold tables
__device__ float gAs [12][NO][8][TC];          // i-folded w_s      [hc][o][j][tc]
__device__ float gAd [12][NO][8][TC];          // i-folded (w_t-w_s)
__device__ float gD0h[12][NO][8][4];           // sum_t gAd         [hc][o][j][c]
__device__ float gD1h[12][NO][8][4];           // sum_t t*gAd

typedef unsigned long long u64;
#define FMA2(d,a,b,c) asm("fma.rn.f32x2 %0, %1, %2, %3;" : "=l"(d) : "l"(a), "l"(b), "l"(c))
#define UNPACK2(lo,hi,v) asm("mov.b64 {%0, %1}, %2;" : "=f"(lo), "=f"(hi) : "l"(v))

__device__ __forceinline__ int class_ilist(int hc, int idx[2]) {
    if (hc < 4)  { idx[0] = hc;                  return 1; }
    if (hc < 8)  { idx[0] = hc - 4; idx[1] = hc; return 2; }
    idx[0] = hc - 4;                             return 1;
}

// ---------------------------------------------------------------------------
// prepA: fold the i axis for all 12 hc classes at once.  18432 threads.
// ---------------------------------------------------------------------------
__global__ void dlinear_prepA(const float* __restrict__ w_s,
                              const float* __restrict__ w_t) {
    int n = blockIdx.x * blockDim.x + threadIdx.x;
    if (n >= NO * T_IN * 4 * 8) return;
    int j  = n & 7;
    int tc_row = n >> 3;            // (o*12+t)*4+c
    int t  = (n >> 5) % 12;
    int o  = (n >> 5) / 12;
    int c  = (n >> 3) & 3;
    int tc = t * 4 + c;

    int base = tc_row * 64 + j;
    float v[8], d[8];
    #pragma unroll
    for (int i = 0; i < 8; i++) {
        float a = w_s[base + 8 * i];
        float b = w_t[base + 8 * i];
        v[i] = a;
        d[i] = b - a;
    }
    #pragma unroll
    for (int m = 0; m < 4; m++) {
        gAs[m][o][j][tc]     = v[m];
        gAs[m + 4][o][j][tc] = v[m] + v[m + 4];
        gAs[m + 8][o][j][tc] = v[m + 4];
        gAd[m][o][j][tc]     = d[m];
        gAd[m + 4][o][j][tc] = d[m] + d[m + 4];
        gAd[m + 8][o][j][tc] = d[m + 4];
    }
}

// ---------------------------------------------------------------------------
// prepA2: (a) t-reduce gAd -> gD0h/gD1h  (b) bias fold -> gBi12
// ---------------------------------------------------------------------------
__global__ void dlinear_prepA2(const float* __restrict__ b_s,
                               const float* __restrict__ b_t) {
    int n = blockIdx.x * blockDim.x + threadIdx.x;
    if (n < 12 * NO * 8 * 4) {
        int c = n & 3, j = (n >> 2) & 7;
        int rest = n >> 5;
        int o = rest % NO, hc = rest / NO;
        float d0 = 0.f, d1 = 0.f;
        #pragma unroll
        for (int t = 0; t < T_IN; t++) {
            float d = gAd[hc][o][j][t * 4 + c];
            d0 += d;
            d1 += (float)t * d;
        }
        gD0h[hc][o][j][c] = d0;
        gD1h[hc][o][j][c] = d1;
        return;
    }
    int m = n - 12 * NO * 8 * 4;
    if (m < NCLS * NO) {
        int o = m % NO, cls = m / NO;
        int hc = cls / 12, wc = cls % 12;
        int il[2], jl[2];
        int ni = class_ilist(hc, il), nj = class_ilist(wc, jl);
        float s = 0.f;
        for (int a = 0; a < ni; a++)
            for (int e = 0; e < nj; e++) {
                int off = o * 64 + il[a] * 8 + jl[e];
                s += b_s[off] + b_t[off];
            }
        gBi12[hc][o >> 2][wc][o & 3] = s;
    }
}

// ---------------------------------------------------------------------------
// prepB: fold the j axis per class + absorb trend -> gWi12.  331776 threads
// (exactly one per output element).
// ---------------------------------------------------------------------------
__global__ void dlinear_prepB() {
    int n = blockIdx.x * blockDim.x + threadIdx.x;
    if (n >= NCLS * NO * TC) return;
    int tc = n % TC;
    int o  = (n / TC) % NO;
    int cls = n / (NO * TC);
    int hc = cls / 12, wc = cls % 12;
    int t = tc >> 2, c = tc & 3;

    int jl[2];
    int nj = class_ilist(wc, jl);

    float s = 0.f, d0 = 0.f, d1 = 0.f;
    for (int e = 0; e < nj; e++) {
        int j = jl[e];
        s  += gAs [hc][o][j][tc];
        d0 += gD0h[hc][o][j][c];
        d1 += gD1h[hc][o][j][c];
    }
    float wv = s + (1.f / 25.f) * d0;
    if (t == 0)  wv += (1.f / 25.f) * (12.f * d0 - d1);
    if (t == 11) wv += (1.f / 25.f) * (d0 + d1);

    gWi12[hc][o][t][wc][c] = wv;
}

// ---------------------------------------------------------------------------
// Main.  128 blocks x 256 threads, 4 px/thread, one wave, all threads active.
//   bid = h*2 + half : h in [0,64), half selects b range [half*16, half*16+16).
//   thread: w = tid&63 (lanes contiguous), rr = tid>>6;
//           pixels at b = half*16 + rr + {0,4,8,12}, fixed (h, w).
// ---------------------------------------------------------------------------
__global__ __launch_bounds__(256, 1)
void dlinear_main_kernel(const float* __restrict__ x, float* __restrict__ out) {
    extern __shared__ float sm[];
    const int tid = threadIdx.x;
    const int bid = blockIdx.x;

    const int h  = bid >> 1;
    const int b0 = (bid & 1) * 16;
    const int hc = (h < 4) ? h : ((h < 60) ? 4 + (h & 3) : 8 + (h & 3));

    // ---- stage weight table (27648 floats) + bias (576) into smem
    {
        const float4* s4 = (const float4*)&gWi12[hc][0][0][0][0];
        float4* d4 = (float4*)sm;
        #pragma unroll
        for (int it = 0; it < 27; it++)
            d4[tid + it * 256] = s4[tid + it * 256];
        const float4* b4 = (const float4*)&gBi12[hc][0][0][0];
        if (tid < 144) ((float4*)(sm + TAB_FLOATS))[tid] = b4[tid];
    }

    const int w  = tid & 63;
    const int rr = tid >> 6;
    const int wc = (w < 4) ? w : ((w < 60) ? 4 + (w & 3) : 8 + (w & 3));

    int g[4];
    #pragma unroll
    for (int it = 0; it < 4; it++) {
        int b = b0 + rr + it * 4;
        g[it] = b * T_IN * HW + h * 64 + w;    // in float4 (16B) units
    }

    __syncthreads();

    // ---- front-batched coalesced loads of x[t][c] for all 4 pixels
    u64 x2[4][24];
    const ulonglong2* xg = (const ulonglong2*)x;
    #pragma unroll
    for (int t = 0; t < T_IN; t++) {
        #pragma unroll
        for (int p = 0; p < 4; p++) {
            ulonglong2 v = xg[g[p] + t * HW];
            x2[p][2 * t] = v.x;  x2[p][2 * t + 1] = v.y;
        }
    }

    // ---- 48 outputs x 4 pixels; lane-slot weight reads within 192B records
    const ulonglong2* wt = (const ulonglong2*)sm;
    const float4* bt = (const float4*)(sm + TAB_FLOATS);
    float4* og = (float4*)out;

    #pragma unroll 1
    for (int to = 0; to < 12; to++) {
        float4 bias = bt[to * 12 + wc];
        const float* bp = (const float*)&bias;
        float res[4][4];
        #pragma unroll
        for (int co = 0; co < 4; co++) {
            const int o = to * 4 + co;
            const ulonglong2* wr = wt + (o * 12) * 12 + wc;
            u64 a0 = 0, a1 = 0, a2 = 0, a3 = 0;
            #pragma unroll
            for (int q = 0; q < 12; q++) {
                ulonglong2 wv = wr[q * 12];
                FMA2(a0, x2[0][2 * q],     wv.x, a0);
                FMA2(a1, x2[1][2 * q],     wv.x, a1);
                FMA2(a2, x2[2][2 * q],     wv.x, a2);
                FMA2(a3, x2[3][2 * q],     wv.x, a3);
                FMA2(a0, x2[0][2 * q + 1], wv.y, a0);
                FMA2(a1, x2[1][2 * q + 1], wv.y, a1);
                FMA2(a2, x2[2][2 * q + 1], wv.y, a2);
                FMA2(a3, x2[3][2 * q + 1], wv.y, a3);
            }
            float lo, hi;
            UNPACK2(lo, hi, a0); res[0][co] = bp[co] + lo + hi;
            UNPACK2(lo, hi, a1); res[1][co] = bp[co] + lo + hi;
            UNPACK2(lo, hi, a2); res[2][co] = bp[co] + lo + hi;
            UNPACK2(lo, hi, a3); res[3][co] = bp[co] + lo + hi;
        }
        #pragma unroll
        for (int p = 0; p < 4; p++)
            og[g[p] + to * HW] = make_float4(res[p][0], res[p][1], res[p][2], res[p][3]);
    }
}

// ---------------------------------------------------------------------------
extern "C" void kernel_launch(void* const* d_in, const int* in_sizes, int n_in,
                              void* d_out, int out_size) {
    const float* x   = (const float*)d_in[0];
    const float* w_s = (const float*)d_in[1];
    const float* b_s = (const float*)d_in[2];
    const float* w_t = (const float*)d_in[3];
    const float* b_t = (const float*)d_in[4];
    float* out = (float*)d_out;

    cudaFuncSetAttribute(dlinear_main_kernel,
                         cudaFuncAttributeMaxDynamicSharedMemorySize, SMEM_BYTES);

    dlinear_prepA <<<72, 256>>>(w_s, w_t);                  // 18432 threads
    dlinear_prepA2<<<100, 256>>>(b_s, b_t);                 // 18432 + 6912
    dlinear_prepB <<<1296, 256>>>();                        // 331776 threads
    dlinear_main_kernel<<<128, 256, SMEM_BYTES>>>(x, out);
}

// round 11
// speedup vs baseline: 1.8174x; 1.0817x over previous
#include <cuda_runtime.h>

// ---------------------------------------------------------------------------
// DLinear_436: per-pixel 48->48 linear map with (hc,wc) position-class weights.
// Trend (window-25 moving avg over T=12, affine in t) folded entirely into the
// weight table by prep.  Prep: separable fold -> 12-slot interleaved table
//   gWi12[hc][o][q][wc][4]   (192B record covers ALL 12 wc classes)
// Main: 128 blocks x 256 threads, 4 px/thread, ONE wave, ALL threads active.
//   Weight table staged via cp.async.bulk (mbarrier), x LDGs hoisted in front
//   of the wait so both DRAM latencies overlap.  FMA2 pipe is the target
//   binding resource.
// ---------------------------------------------------------------------------

#define T_IN 12
#define HW   4096
#define NO   48
#define TC   48
#define NCLS 144

#define TAB_FLOATS (48 * 12 * 12 * 4)          // 27648
#define TAB_BYTES  (TAB_FLOATS * 4)            // 110592
#define BIAS_BYTES (576 * 4)                   // 2304
#define SMEM_FLOATS (TAB_FLOATS + 576)         // 28224
#define SMEM_BYTES  (SMEM_FLOATS * 4 + 16)     // + mbarrier

// Final tables
__device__ float gWi12[12][48][12][12][4];     // [hc][o][q][wc][c]
__device__ float gBi12[12][12][12][4];         // [hc][to][wc][co]
// Intermediate separable-fold tables
__device__ float gAs [12][NO][8][TC];          // i-folded w_s      [hc][o][j][tc]
__device__ float gAd [12][NO][8][TC];          // i-folded (w_t-w_s)

typedef unsigned long long u64;
#define FMA2(d,a,b,c) asm("fma.rn.f32x2 %0, %1, %2, %3;" : "=l"(d) : "l"(a), "l"(b), "l"(c))
#define UNPACK2(lo,hi,v) asm("mov.b64 {%0, %1}, %2;" : "=f"(lo), "=f"(hi) : "l"(v))

__device__ __forceinline__ unsigned smem_u32(const void* p) {
    unsigned a;
    asm("{ .reg .u64 t; cvta.to.shared.u64 t, %1; cvt.u32.u64 %0, t; }"
        : "=r"(a) : "l"(p));
    return a;
}

__device__ __forceinline__ int class_ilist(int hc, int idx[2]) {
    if (hc < 4)  { idx[0] = hc;                  return 1; }
    if (hc < 8)  { idx[0] = hc - 4; idx[1] = hc; return 2; }
    idx[0] = hc - 4;                             return 1;
}

// ---------------------------------------------------------------------------
// prepA: fold the i axis for all 12 hc classes at once.  18432 threads.
// ---------------------------------------------------------------------------
__global__ void dlinear_prepA(const float* __restrict__ w_s,
                              const float* __restrict__ w_t) {
    int n = blockIdx.x * blockDim.x + threadIdx.x;
    if (n >= NO * T_IN * 4 * 8) return;
    int j  = n & 7;
    int tc_row = n >> 3;            // (o*12+t)*4+c
    int t  = (n >> 5) % 12;
    int o  = (n >> 5) / 12;
    int c  = (n >> 3) & 3;
    int tc = t * 4 + c;

    int base = tc_row * 64 + j;
    float v[8], d[8];
    #pragma unroll
    for (int i = 0; i < 8; i++) {
        float a = w_s[base + 8 * i];
        float b = w_t[base + 8 * i];
        v[i] = a;
        d[i] = b - a;
    }
    #pragma unroll
    for (int m = 0; m < 4; m++) {
        gAs[m][o][j][tc]     = v[m];
        gAs[m + 4][o][j][tc] = v[m] + v[m + 4];
        gAs[m + 8][o][j][tc] = v[m + 4];
        gAd[m][o][j][tc]     = d[m];
        gAd[m + 4][o][j][tc] = d[m] + d[m + 4];
        gAd[m + 8][o][j][tc] = d[m + 4];
    }
}

// ---------------------------------------------------------------------------
// prepB: fold j axis per class, inline t-reduction of gAd (L1-broadcast
// heavy reuse across the warp), absorb trend -> gWi12.  Tail threads fold
// the bias.  338688 threads.
// ---------------------------------------------------------------------------
__global__ void dlinear_prepB(const float* __restrict__ b_s,
                              const float* __restrict__ b_t) {
    int n = blockIdx.x * blockDim.x + threadIdx.x;
    if (n < NCLS * NO * TC) {
        int tc = n % TC;
        int o  = (n / TC) % NO;
        int cls = n / (NO * TC);
        int hc = cls / 12, wc = cls % 12;
        int t = tc >> 2, c = tc & 3;

        int jl[2];
        int nj = class_ilist(wc, jl);

        float s = 0.f, d0 = 0.f, d1 = 0.f;
        for (int e = 0; e < nj; e++) {
            int j = jl[e];
            s += gAs[hc][o][j][tc];
            #pragma unroll
            for (int tt = 0; tt < T_IN; tt++) {
                float d = gAd[hc][o][j][tt * 4 + c];
                d0 += d;
                d1 += (float)tt * d;
            }
        }
        float wv = s + (1.f / 25.f) * d0;
        if (t == 0)  wv += (1.f / 25.f) * (12.f * d0 - d1);
        if (t == 11) wv += (1.f / 25.f) * (d0 + d1);
        gWi12[hc][o][t][wc][c] = wv;
        return;
    }
    int m = n - NCLS * NO * TC;
    if (m < NCLS * NO) {
        int o = m % NO, cls = m / NO;
        int hc = cls / 12, wc = cls % 12;
        int il[2], jl[2];
        int ni = class_ilist(hc, il), nj = class_ilist(wc, jl);
        float s = 0.f;
        for (int a = 0; a < ni; a++)
            for (int e = 0; e < nj; e++) {
                int off = o * 64 + il[a] * 8 + jl[e];
                s += b_s[off] + b_t[off];
            }
        gBi12[hc][o >> 2][wc][o & 3] = s;
    }
}

// ---------------------------------------------------------------------------
// Main.  128 blocks x 256 threads, 4 px/thread, one wave, all threads active.
//   bid = h*2 + half : h in [0,64), half selects b range [half*16, +16).
//   thread: w = tid&63 (lanes contiguous), rr = tid>>6;
//           pixels at b = half*16 + rr + {0,4,8,12}, fixed (h, w).
// Weight table + bias arrive by cp.async.bulk; x LDGs overlap the copy.
// ---------------------------------------------------------------------------
__global__ __launch_bounds__(256, 1)
void dlinear_main_kernel(const float* __restrict__ x, float* __restrict__ out) {
    extern __shared__ float sm[];
    const int tid = threadIdx.x;
    const int bid = blockIdx.x;

    const int h  = bid >> 1;
    const int b0 = (bid & 1) * 16;
    const int hc = (h < 4) ? h : ((h < 60) ? 4 + (h & 3) : 8 + (h & 3));

    const unsigned mbar = smem_u32(sm + SMEM_FLOATS);

    if (tid == 0) {
        asm volatile("mbarrier.init.shared.b64 [%0], 1;" :: "r"(mbar) : "memory");
    }
    __syncthreads();
    if (tid == 0) {
        asm volatile("mbarrier.arrive.expect_tx.shared.b64 _, [%0], %1;"
                     :: "r"(mbar), "r"((unsigned)(TAB_BYTES + BIAS_BYTES)) : "memory");
        asm volatile("cp.async.bulk.shared::cta.global.mbarrier::complete_tx::bytes "
                     "[%0], [%1], %2, [%3];"
                     :: "r"(smem_u32(sm)), "l"(&gWi12[hc][0][0][0][0]),
                        "r"((unsigned)TAB_BYTES), "r"(mbar) : "memory");
        asm volatile("cp.async.bulk.shared::cta.global.mbarrier::complete_tx::bytes "
                     "[%0], [%1], %2, [%3];"
                     :: "r"(smem_u32(sm + TAB_FLOATS)), "l"(&gBi12[hc][0][0][0]),
                        "r"((unsigned)BIAS_BYTES), "r"(mbar) : "memory");
    }

    const int w  = tid & 63;
    const int rr = tid >> 6;
    const int wc = (w < 4) ? w : ((w < 60) ? 4 + (w & 3) : 8 + (w & 3));

    int g[4];
    #pragma unroll
    for (int it = 0; it < 4; it++) {
        int b = b0 + rr + it * 4;
        g[it] = b * T_IN * HW + h * 64 + w;    // in float4 (16B) units
    }

    // ---- x LDGs issued while the bulk copy streams in
    u64 x2[4][24];
    const ulonglong2* xg = (const ulonglong2*)x;
    #pragma unroll
    for (int t = 0; t < T_IN; t++) {
        #pragma unroll
        for (int p = 0; p < 4; p++) {
            ulonglong2 v = xg[g[p] + t * HW];
            x2[p][2 * t] = v.x;  x2[p][2 * t + 1] = v.y;
        }
    }

    // ---- wait for the weight table (acquire orders subsequent smem reads)
    asm volatile(
        "{\n\t"
        ".reg .pred p;\n\t"
        "WAIT_%=:\n\t"
        "mbarrier.try_wait.parity.acquire.cta.shared::cta.b64 p, [%0], 0, 0x989680;\n\t"
        "@!p bra WAIT_%=;\n\t"
        "}" :: "r"(mbar) : "memory");

    // ---- 48 outputs x 4 pixels; lane-slot weight reads within 192B records
    const ulonglong2* wt = (const ulonglong2*)sm;
    const float4* bt = (const float4*)(sm + TAB_FLOATS);
    float4* og = (float4*)out;

    #pragma unroll 1
    for (int to = 0; to < 12; to++) {
        float4 bias = bt[to * 12 + wc];
        const float* bp = (const float*)&bias;
        float res[4][4];
        #pragma unroll
        for (int co = 0; co < 4; co++) {
            const int o = to * 4 + co;
            const ulonglong2* wr = wt + (o * 12) * 12 + wc;
            u64 a0 = 0, a1 = 0, a2 = 0, a3 = 0;
            #pragma unroll
            for (int q = 0; q < 12; q++) {
                ulonglong2 wv = wr[q * 12];
                FMA2(a0, x2[0][2 * q],     wv.x, a0);
                FMA2(a1, x2[1][2 * q],     wv.x, a1);
                FMA2(a2, x2[2][2 * q],     wv.x, a2);
                FMA2(a3, x2[3][2 * q],     wv.x, a3);
                FMA2(a0, x2[0][2 * q + 1], wv.y, a0);
                FMA2(a1, x2[1][2 * q + 1], wv.y, a1);
                FMA2(a2, x2[2][2 * q + 1], wv.y, a2);
                FMA2(a3, x2[3][2 * q + 1], wv.y, a3);
            }
            float lo, hi;
            UNPACK2(lo, hi, a0); res[0][co] = bp[co] + lo + hi;
            UNPACK2(lo, hi, a1); res[1][co] = bp[co] + lo + hi;
            UNPACK2(lo, hi, a2); res[2][co] = bp[co] + lo + hi;
            UNPACK2(lo, hi, a3); res[3][co] = bp[co] + lo + hi;
        }
        #pragma unroll
        for (int p = 0; p < 4; p++)
            og[g[p] + to * HW] = make_float4(res[p][0], res[p][1], res[p][2], res[p][3]);
    }
}

// ---------------------------------------------------------------------------
extern "C" void kernel_launch(void* const* d_in, const int* in_sizes, int n_in,
                              void* d_out, int out_size) {
    const float* x   = (const float*)d_in[0];
    const float* w_s = (const float*)d_in[1];
    const float* b_s = (const float*)d_in[2];
    const float* w_t = (const float*)d_in[3];
    const float* b_t = (const float*)d_in[4];
    float* out = (float*)d_out;

    cudaFuncSetAttribute(dlinear_main_kernel,
                         cudaFuncAttributeMaxDynamicSharedMemorySize, SMEM_BYTES);

    dlinear_prepA<<<72, 256>>>(w_s, w_t);                   // 18432 threads
    dlinear_prepB<<<1323, 256>>>(b_s, b_t);                 // 331776 + 6912
    dlinear_main_kernel<<<128, 256, SMEM_BYTES>>>(x, out);
}